// round 1
// baseline (speedup 1.0000x reference)
#include <cuda_runtime.h>
#include <cuda_bf16.h>
#include <math.h>
#include <float.h>

// ---------------------------------------------------------------------------
// Problem constants
// ---------------------------------------------------------------------------
#define NS   4096        // samples
#define IND  768         // input dim
#define DD   256         // prototype dim
#define PP   64          // prototypes
#define PPOS 32          // P/2

// ---------------------------------------------------------------------------
// Device scratch (static — no runtime allocation allowed)
// ---------------------------------------------------------------------------
__device__ float        g_zpart[3][NS][DD];   // split-K partials of z (12 MB)
__device__ float        g_cos[NS * PP];       // cosine similarities (1 MB)
__device__ float        g_pnorm2[PP];
__device__ float        g_pnorm_inv[PP];      // 1 / max(||p||, eps)
__device__ unsigned int g_minBits[PP];        // per-prototype min dist (bits)
__device__ float        g_pp_sum;
__device__ float        g_pz_sum;
__device__ float        g_cl_sum;
__device__ int          g_num_cnt;

__device__ __forceinline__ float warpSum(float v) {
#pragma unroll
    for (int o = 16; o; o >>= 1) v += __shfl_xor_sync(0xffffffffu, v, o);
    return v;
}

// ---------------------------------------------------------------------------
// K_init: zero accumulators, set per-prototype mins to +FLT_MAX
// ---------------------------------------------------------------------------
__global__ void k_init() {
    int t = threadIdx.x;
    if (t < PP) g_minBits[t] = 0x7f7fffffu;  // FLT_MAX bits (dists are >= 0)
    if (t == 0) {
        g_pp_sum = 0.f; g_pz_sum = 0.f; g_cl_sum = 0.f; g_num_cnt = 0;
    }
}

// ---------------------------------------------------------------------------
// K_proto: per-prototype norms + pairwise-distance loss (l_pp numerator)
// grid = 64 blocks (one per prototype i), 256 threads
// ---------------------------------------------------------------------------
__global__ void k_proto(const float* __restrict__ proto) {
    const int i = blockIdx.x;
    const int t = threadIdx.x;
    __shared__ float pi[DD];
    __shared__ float red[8];
    __shared__ float ddist[PP];

    // stage prototype i, accumulate ||p_i||^2
    float v = proto[i * DD + t];
    pi[t] = v;
    float nrm = warpSum(v * v);
    if ((t & 31) == 0) red[t >> 5] = nrm;
    __syncthreads();
    if (t == 0) {
        float s = 0.f;
#pragma unroll
        for (int w = 0; w < 8; w++) s += red[w];
        g_pnorm2[i]    = s;
        g_pnorm_inv[i] = 1.0f / fmaxf(sqrtf(s), 1e-8f);
    }
    __syncthreads();

    // pairwise distances: thread t -> prototype j = t/4, quarter q = t&3
    const int j = t >> 2;
    const int q = t & 3;
    const float* pj = proto + j * DD + q * 64;
    float s = 0.f;
#pragma unroll 8
    for (int d = 0; d < 64; d++) {
        float df = pi[q * 64 + d] - pj[d];
        s += df * df;
    }
    // combine the 4 quarters (lanes q,q+1,q+2,q+3 contiguous in warp)
    s += __shfl_down_sync(0xffffffffu, s, 1);
    s += __shfl_down_sync(0xffffffffu, s, 2);
    if (q == 0) ddist[j] = (j == i) ? 0.f : sqrtf(fmaxf(s, 0.f));
    __syncthreads();
    if (t == 0) {
        float acc = 0.f;
#pragma unroll
        for (int k = 0; k < PP; k++) acc += ddist[k];
        atomicAdd(&g_pp_sum, acc);
    }
}

// ---------------------------------------------------------------------------
// K_gemm: z-partial = x[.,kchunk] @ W[kchunk,.] (+ bias on chunk 0)
// tiles 128x128, K chunk = 256, grid (32, 2, 3), 256 threads, 8x8/thread
// ---------------------------------------------------------------------------
__global__ __launch_bounds__(256, 2)
void k_gemm(const float* __restrict__ X, const float* __restrict__ W,
            const float* __restrict__ bias) {
    __shared__ float As[16][132];   // [k][m], padded for bank-conflict-free
    __shared__ float Bs[16][128];   // [k][n]

    const int m0 = blockIdx.x * 128;
    const int n0 = blockIdx.y * 128;
    const int kc = blockIdx.z;
    const int k0 = kc * 256;

    const int tid = threadIdx.x;
    const int tx = tid & 15, ty = tid >> 4;

    // A-load mapping: 128 rows x 16 cols, float4 along k
    const int arow = tid >> 2;          // 0..63 (+64 on 2nd iter)
    const int acol = (tid & 3) * 4;     // 0,4,8,12
    // B-load mapping: 16 rows x 128 cols, float4 along n
    const int brow = tid >> 5;          // 0..7 (+8 on 2nd iter)
    const int bcol = (tid & 31) * 4;

    float acc[8][8];
#pragma unroll
    for (int i = 0; i < 8; i++)
#pragma unroll
        for (int j = 0; j < 8; j++) acc[i][j] = 0.f;

    for (int kt = 0; kt < 256; kt += 16) {
#pragma unroll
        for (int r = 0; r < 2; r++) {
            const float4 v = *(const float4*)&X[(size_t)(m0 + arow + r * 64) * IND + k0 + kt + acol];
            As[acol + 0][arow + r * 64] = v.x;
            As[acol + 1][arow + r * 64] = v.y;
            As[acol + 2][arow + r * 64] = v.z;
            As[acol + 3][arow + r * 64] = v.w;
        }
#pragma unroll
        for (int r = 0; r < 2; r++) {
            *(float4*)&Bs[brow + r * 8][bcol] =
                *(const float4*)&W[(size_t)(k0 + kt + brow + r * 8) * DD + n0 + bcol];
        }
        __syncthreads();
#pragma unroll
        for (int kk = 0; kk < 16; kk++) {
            float a[8], b[8];
            *(float4*)&a[0] = *(const float4*)&As[kk][ty * 8];
            *(float4*)&a[4] = *(const float4*)&As[kk][ty * 8 + 4];
            *(float4*)&b[0] = *(const float4*)&Bs[kk][tx * 8];
            *(float4*)&b[4] = *(const float4*)&Bs[kk][tx * 8 + 4];
#pragma unroll
            for (int i = 0; i < 8; i++)
#pragma unroll
                for (int j = 0; j < 8; j++) acc[i][j] += a[i] * b[j];
        }
        __syncthreads();
    }

    float bj[8];
#pragma unroll
    for (int j = 0; j < 8; j++)
        bj[j] = (kc == 0) ? bias[n0 + tx * 8 + j] : 0.f;

    float* zc = &g_zpart[kc][0][0];
#pragma unroll
    for (int i = 0; i < 8; i++) {
        const int m = m0 + ty * 8 + i;
        float* orow = zc + (size_t)m * DD + n0 + tx * 8;
        float4 v0 = make_float4(acc[i][0] + bj[0], acc[i][1] + bj[1],
                                acc[i][2] + bj[2], acc[i][3] + bj[3]);
        float4 v1 = make_float4(acc[i][4] + bj[4], acc[i][5] + bj[5],
                                acc[i][6] + bj[6], acc[i][7] + bj[7]);
        *(float4*)&orow[0] = v0;
        *(float4*)&orow[4] = v1;
    }
}

// ---------------------------------------------------------------------------
// K_stats: per-sample cos/dist, all reductions. Warp per sample.
// grid = 512 blocks x 256 threads (8 warps = 8 samples per block)
// ---------------------------------------------------------------------------
__global__ __launch_bounds__(256)
void k_stats(const float* __restrict__ proto, const long long* __restrict__ labels) {
    __shared__ unsigned int bmin[PP];
    const int tid = threadIdx.x;
    if (tid < PP) bmin[tid] = 0x7f7fffffu;
    __syncthreads();

    const int warp = tid >> 5, lane = tid & 31;
    const int n = blockIdx.x * 8 + warp;

    // z row: sum 3 split-K partials; d = lane*8 + j
    const float* z0 = &g_zpart[0][0][0] + (size_t)n * DD + lane * 8;
    const float* z1 = z0 + (size_t)NS * DD;
    const float* z2 = z1 + (size_t)NS * DD;
    float z[8];
    {
        float4 a0 = *(const float4*)(z0);     float4 a1 = *(const float4*)(z1);
        float4 a2 = *(const float4*)(z2);
        z[0] = a0.x + a1.x + a2.x; z[1] = a0.y + a1.y + a2.y;
        z[2] = a0.z + a1.z + a2.z; z[3] = a0.w + a1.w + a2.w;
        float4 b0 = *(const float4*)(z0 + 4); float4 b1 = *(const float4*)(z1 + 4);
        float4 b2 = *(const float4*)(z2 + 4);
        z[4] = b0.x + b1.x + b2.x; z[5] = b0.y + b1.y + b2.y;
        z[6] = b0.z + b1.z + b2.z; z[7] = b0.w + b1.w + b2.w;
    }
    float s2 = 0.f;
#pragma unroll
    for (int j = 0; j < 8; j++) s2 += z[j] * z[j];
    const float zn2 = warpSum(s2);
    const float rz  = 1.0f / fmaxf(sqrtf(zn2), 1e-8f);

    float c0 = 0.f, c1 = 0.f, d0 = 0.f, d1 = 0.f;
    float minD = FLT_MAX, maxPos = -FLT_MAX, maxNeg = -FLT_MAX;
    int cnt = 0;

#pragma unroll 8
    for (int p = 0; p < PP; p++) {
        const float* pr = proto + p * DD + lane * 8;
        const float4 q0 = __ldg((const float4*)pr);
        const float4 q1 = __ldg((const float4*)(pr + 4));
        float part = z[0] * q0.x + z[1] * q0.y + z[2] * q0.z + z[3] * q0.w
                   + z[4] * q1.x + z[5] * q1.y + z[6] * q1.z + z[7] * q1.w;
        const float dot = warpSum(part);            // broadcast to all lanes
        const float pn2 = g_pnorm2[p];
        const float cosv = dot * rz * g_pnorm_inv[p];
        const float dist = sqrtf(fmaxf(zn2 + pn2 - 2.0f * dot, 0.f));
        minD = fminf(minD, dist);
        if (p < PPOS) maxPos = fmaxf(maxPos, cosv);
        else          maxNeg = fmaxf(maxNeg, cosv);
        cnt += (cosv > 0.5f);
        if (p == lane)      { c0 = cosv; d0 = dist; }
        if (p == lane + 32) { c1 = cosv; d1 = dist; }
    }

    g_cos[n * PP + lane]      = c0;
    g_cos[n * PP + lane + 32] = c1;
    atomicMin(&bmin[lane],      __float_as_uint(d0));
    atomicMin(&bmin[lane + 32], __float_as_uint(d1));

    if (lane == 0) {
        atomicAdd(&g_pz_sum, minD);
        const long long lb = labels[n];
        atomicAdd(&g_cl_sum, (lb == 1) ? (1.0f - maxPos) : (1.0f - maxNeg));
        if (cnt > 16) atomicAdd(&g_num_cnt, 1);   // num_sim > P/4
    }
    __syncthreads();
    if (tid < PP) atomicMin(&g_minBits[tid], bmin[tid]);
}

// ---------------------------------------------------------------------------
// K_tokens: token_sequences[n,p,d] = cos[n,p] * proto[p,d]  (268 MB stream)
// grid = 65536 x 256, one float4 per thread
// ---------------------------------------------------------------------------
__global__ __launch_bounds__(256)
void k_tokens(const float* __restrict__ proto, float* __restrict__ out) {
    const int i  = blockIdx.x * 256 + threadIdx.x;  // float4 index
    const int d4 = i & 63;
    const int p  = (i >> 6) & 63;
    const float c = __ldg(&g_cos[i >> 6]);          // (n*64 + p) == i>>6
    const float4 pr = __ldg((const float4*)proto + p * 64 + d4);
    float4 v = make_float4(c * pr.x, c * pr.y, c * pr.z, c * pr.w);
    ((float4*)out)[i] = v;
}

// ---------------------------------------------------------------------------
// K_final: combine scalar loss terms
// ---------------------------------------------------------------------------
__global__ void k_final(float* __restrict__ out, int loss_idx) {
    __shared__ float s[PP];
    const int t = threadIdx.x;
    if (t < PP) s[t] = __uint_as_float(g_minBits[t]);
    __syncthreads();
    if (t == 0) {
        float zp = 0.f;
#pragma unroll
        for (int k = 0; k < PP; k++) zp += s[k];
        const float l_zp  = zp / (float)PP;
        const float l_pz  = g_pz_sum / (float)NS;
        const float l_pp  = g_pp_sum / (float)(PP * (PP - 1));
        const float l_num = (float)g_num_cnt;
        const float l_cl  = g_cl_sum / (float)NS;
        // weights all 1.0; cluster loss counted twice (W_CLUSTER + W_SEP)
        out[loss_idx] = l_zp + l_pz + l_pp + l_num + l_cl + l_cl;
    }
}

// ---------------------------------------------------------------------------
// kernel_launch
// ---------------------------------------------------------------------------
extern "C" void kernel_launch(void* const* d_in, const int* in_sizes, int n_in,
                              void* d_out, int out_size) {
    // identify inputs by element count (all distinct)
    const float*     x      = nullptr;
    const long long* labels = nullptr;
    const float*     W      = nullptr;
    const float*     b      = nullptr;
    const float*     proto  = nullptr;
    for (int i = 0; i < n_in; i++) {
        switch (in_sizes[i]) {
            case NS * IND: x      = (const float*)d_in[i];     break; // 3145728
            case NS:       labels = (const long long*)d_in[i]; break; // 4096
            case IND * DD: W      = (const float*)d_in[i];     break; // 196608
            case DD:       b      = (const float*)d_in[i];     break; // 256
            case PP * DD:  proto  = (const float*)d_in[i];     break; // 16384
        }
    }
    if (!x || !labels || !W || !b || !proto) {
        // fall back to positional order {x, labels, W, b, prototypes}
        x      = (const float*)d_in[0];
        labels = (const long long*)d_in[1];
        W      = (const float*)d_in[2];
        b      = (const float*)d_in[3];
        proto  = (const float*)d_in[4];
    }
    float* out = (float*)d_out;

    k_init  <<<1, 64>>>();
    k_proto <<<PP, 256>>>(proto);
    k_gemm  <<<dim3(NS / 128, DD / 128, 3), 256>>>(x, W, b);
    k_stats <<<NS / 8, 256>>>(proto, labels);
    k_tokens<<<(NS * PP * DD / 4) / 256, 256>>>(proto, out);
    k_final <<<1, 64>>>(out, out_size - 1);
}

// round 2
// speedup vs baseline: 1.1735x; 1.1735x over previous
#include <cuda_runtime.h>
#include <cuda_bf16.h>
#include <math.h>
#include <float.h>

// ---------------------------------------------------------------------------
// Problem constants
// ---------------------------------------------------------------------------
#define NS   4096        // samples
#define IND  768         // input dim
#define DD   256         // prototype dim
#define PP   64          // prototypes
#define PPOS 32          // P/2
#define NSK  4           // split-K factor
#define KCH  (IND / NSK) // 192 (12 tiles of 16)

// ---------------------------------------------------------------------------
// Device scratch (static — no runtime allocation allowed)
// ---------------------------------------------------------------------------
__device__ float        g_zpart[NSK][NS][DD]; // split-K partials of z (16 MB)
__device__ float        g_cos[NS * PP];       // cosine similarities (1 MB)
__device__ float        g_pnorm2[PP];
__device__ float        g_pnorm_inv[PP];      // 1 / max(||p||, eps)
__device__ unsigned int g_minBits[PP];        // per-prototype min dist (bits)
__device__ float        g_pp_sum;
__device__ float        g_pz_sum;
__device__ float        g_cl_sum;
__device__ int          g_num_cnt;

__device__ __forceinline__ float warpSum(float v) {
#pragma unroll
    for (int o = 16; o; o >>= 1) v += __shfl_xor_sync(0xffffffffu, v, o);
    return v;
}

// ---------------------------------------------------------------------------
// K_init
// ---------------------------------------------------------------------------
__global__ void k_init() {
    int t = threadIdx.x;
    if (t < PP) g_minBits[t] = 0x7f7fffffu;  // FLT_MAX bits (dists are >= 0)
    if (t == 0) {
        g_pp_sum = 0.f; g_pz_sum = 0.f; g_cl_sum = 0.f; g_num_cnt = 0;
    }
}

// ---------------------------------------------------------------------------
// K_proto: per-prototype norms + pairwise-distance loss (l_pp numerator)
// ---------------------------------------------------------------------------
__global__ void k_proto(const float* __restrict__ proto) {
    const int i = blockIdx.x;
    const int t = threadIdx.x;
    __shared__ float pi[DD];
    __shared__ float red[8];
    __shared__ float ddist[PP];

    float v = proto[i * DD + t];
    pi[t] = v;
    float nrm = warpSum(v * v);
    if ((t & 31) == 0) red[t >> 5] = nrm;
    __syncthreads();
    if (t == 0) {
        float s = 0.f;
#pragma unroll
        for (int w = 0; w < 8; w++) s += red[w];
        g_pnorm2[i]    = s;
        g_pnorm_inv[i] = 1.0f / fmaxf(sqrtf(s), 1e-8f);
    }
    __syncthreads();

    const int j = t >> 2;
    const int q = t & 3;
    const float* pj = proto + j * DD + q * 64;
    float s = 0.f;
#pragma unroll 8
    for (int d = 0; d < 64; d++) {
        float df = pi[q * 64 + d] - pj[d];
        s += df * df;
    }
    s += __shfl_down_sync(0xffffffffu, s, 1);
    s += __shfl_down_sync(0xffffffffu, s, 2);
    if (q == 0) ddist[j] = (j == i) ? 0.f : sqrtf(fmaxf(s, 0.f));
    __syncthreads();
    if (t == 0) {
        float acc = 0.f;
#pragma unroll
        for (int k = 0; k < PP; k++) acc += ddist[k];
        atomicAdd(&g_pp_sum, acc);
    }
}

// ---------------------------------------------------------------------------
// K_gemm: z-partial = x[.,kchunk] @ W[kchunk,.] (+ bias on chunk 0)
// tiles 128x128, K chunk = 192, grid (32, 2, 4) = 256 blocks, 256 threads,
// 8x8/thread, double-buffered smem + register prefetch.
// ---------------------------------------------------------------------------
__global__ __launch_bounds__(256, 2)
void k_gemm(const float* __restrict__ X, const float* __restrict__ W,
            const float* __restrict__ bias) {
    __shared__ float As[2][16][132];   // [buf][k][m], padded
    __shared__ float Bs[2][16][128];   // [buf][k][n]

    const int m0 = blockIdx.x * 128;
    const int n0 = blockIdx.y * 128;
    const int kc = blockIdx.z;
    const int k0 = kc * KCH;

    const int tid = threadIdx.x;
    const int tx = tid & 15, ty = tid >> 4;

    const int arow = tid >> 2;          // 0..63 (+64 on 2nd)
    const int acol = (tid & 3) * 4;     // 0,4,8,12
    const int brow = tid >> 5;          // 0..7 (+8 on 2nd)
    const int bcol = (tid & 31) * 4;

    float4 ra0, ra1, rb0, rb1;

    // prefetch tile 0
    {
        const int kk = k0;
        ra0 = *(const float4*)&X[(size_t)(m0 + arow)      * IND + kk + acol];
        ra1 = *(const float4*)&X[(size_t)(m0 + arow + 64) * IND + kk + acol];
        rb0 = *(const float4*)&W[(size_t)(kk + brow)     * DD + n0 + bcol];
        rb1 = *(const float4*)&W[(size_t)(kk + brow + 8) * DD + n0 + bcol];
    }
    As[0][acol + 0][arow]      = ra0.x;
    As[0][acol + 1][arow]      = ra0.y;
    As[0][acol + 2][arow]      = ra0.z;
    As[0][acol + 3][arow]      = ra0.w;
    As[0][acol + 0][arow + 64] = ra1.x;
    As[0][acol + 1][arow + 64] = ra1.y;
    As[0][acol + 2][arow + 64] = ra1.z;
    As[0][acol + 3][arow + 64] = ra1.w;
    *(float4*)&Bs[0][brow][bcol]     = rb0;
    *(float4*)&Bs[0][brow + 8][bcol] = rb1;
    __syncthreads();

    float acc[8][8];
#pragma unroll
    for (int i = 0; i < 8; i++)
#pragma unroll
        for (int j = 0; j < 8; j++) acc[i][j] = 0.f;

    const int NT = KCH / 16;  // 12
#pragma unroll 2
    for (int t = 0; t < NT; t++) {
        const int buf = t & 1;
        const bool more = (t + 1 < NT);
        if (more) {
            const int kk = k0 + (t + 1) * 16;
            ra0 = *(const float4*)&X[(size_t)(m0 + arow)      * IND + kk + acol];
            ra1 = *(const float4*)&X[(size_t)(m0 + arow + 64) * IND + kk + acol];
            rb0 = *(const float4*)&W[(size_t)(kk + brow)     * DD + n0 + bcol];
            rb1 = *(const float4*)&W[(size_t)(kk + brow + 8) * DD + n0 + bcol];
        }
#pragma unroll
        for (int kk = 0; kk < 16; kk++) {
            float a[8], b[8];
            *(float4*)&a[0] = *(const float4*)&As[buf][kk][ty * 8];
            *(float4*)&a[4] = *(const float4*)&As[buf][kk][ty * 8 + 4];
            *(float4*)&b[0] = *(const float4*)&Bs[buf][kk][tx * 8];
            *(float4*)&b[4] = *(const float4*)&Bs[buf][kk][tx * 8 + 4];
#pragma unroll
            for (int i = 0; i < 8; i++)
#pragma unroll
                for (int j = 0; j < 8; j++) acc[i][j] += a[i] * b[j];
        }
        if (more) {
            const int nb = buf ^ 1;
            As[nb][acol + 0][arow]      = ra0.x;
            As[nb][acol + 1][arow]      = ra0.y;
            As[nb][acol + 2][arow]      = ra0.z;
            As[nb][acol + 3][arow]      = ra0.w;
            As[nb][acol + 0][arow + 64] = ra1.x;
            As[nb][acol + 1][arow + 64] = ra1.y;
            As[nb][acol + 2][arow + 64] = ra1.z;
            As[nb][acol + 3][arow + 64] = ra1.w;
            *(float4*)&Bs[nb][brow][bcol]     = rb0;
            *(float4*)&Bs[nb][brow + 8][bcol] = rb1;
        }
        __syncthreads();
    }

    float bj[8];
#pragma unroll
    for (int j = 0; j < 8; j++)
        bj[j] = (kc == 0) ? bias[n0 + tx * 8 + j] : 0.f;

    float* zc = &g_zpart[kc][0][0];
#pragma unroll
    for (int i = 0; i < 8; i++) {
        const int m = m0 + ty * 8 + i;
        float* orow = zc + (size_t)m * DD + n0 + tx * 8;
        float4 v0 = make_float4(acc[i][0] + bj[0], acc[i][1] + bj[1],
                                acc[i][2] + bj[2], acc[i][3] + bj[3]);
        float4 v1 = make_float4(acc[i][4] + bj[4], acc[i][5] + bj[5],
                                acc[i][6] + bj[6], acc[i][7] + bj[7]);
        *(float4*)&orow[0] = v0;
        *(float4*)&orow[4] = v1;
    }
}

// ---------------------------------------------------------------------------
// K_stats: warp per sample. Lane accumulates partial dots for ALL 64
// prototypes over its 8-d slice, then a 5-step batched butterfly reduces all
// 64 jointly (62 shuffles, independent — no serialized warpSum chains).
// grid = 512 blocks x 256 threads
// ---------------------------------------------------------------------------
__global__ __launch_bounds__(256, 2)
void k_stats(const float* __restrict__ proto, const long long* __restrict__ labels) {
    __shared__ unsigned int bmin[PP];
    const int tid = threadIdx.x;
    if (tid < PP) bmin[tid] = 0x7f7fffffu;
    __syncthreads();

    const int warp = tid >> 5, lane = tid & 31;
    const int n = blockIdx.x * 8 + warp;

    // z row (d = lane*8 + j): sum the NSK split-K partials
    float z[8];
    {
        const float* zp = &g_zpart[0][0][0] + (size_t)n * DD + lane * 8;
        float4 a = *(const float4*)(zp);
        float4 b = *(const float4*)(zp + 4);
        z[0] = a.x; z[1] = a.y; z[2] = a.z; z[3] = a.w;
        z[4] = b.x; z[5] = b.y; z[6] = b.z; z[7] = b.w;
#pragma unroll
        for (int c = 1; c < NSK; c++) {
            const float* zq = zp + (size_t)c * NS * DD;
            float4 u = *(const float4*)(zq);
            float4 v = *(const float4*)(zq + 4);
            z[0] += u.x; z[1] += u.y; z[2] += u.z; z[3] += u.w;
            z[4] += v.x; z[5] += v.y; z[6] += v.z; z[7] += v.w;
        }
    }
    float s2 = 0.f;
#pragma unroll
    for (int j = 0; j < 8; j++) s2 += z[j] * z[j];
    const float zn2 = warpSum(s2);
    const float rz  = 1.0f / fmaxf(sqrtf(zn2), 1e-8f);

    // partial dots for all 64 prototypes (full ILP, no reductions yet)
    float acc[PP];
    const float4* p4 = (const float4*)proto;
#pragma unroll
    for (int p = 0; p < PP; p++) {
        const float4 q0 = __ldg(p4 + p * 64 + lane * 2);
        const float4 q1 = __ldg(p4 + p * 64 + lane * 2 + 1);
        acc[p] = z[0] * q0.x + z[1] * q0.y + z[2] * q0.z + z[3] * q0.w
               + z[4] * q1.x + z[5] * q1.y + z[6] * q1.z + z[7] * q1.w;
    }

    // batched butterfly: 62 independent shuffles reduce all 64 dots
#pragma unroll
    for (int s = 0; s < 5; s++) {
        const int o = 1 << s;
        const int c = 32 >> s;          // count after this step
        const bool hi = (lane & o) != 0;
#pragma unroll
        for (int i = 0; i < c; i++) {
            const float give = hi ? acc[i] : acc[i + c];
            const float keep = hi ? acc[i + c] : acc[i];
            acc[i] = keep + __shfl_xor_sync(0xffffffffu, give, o);
        }
    }
    // lane now holds full dots for prototypes pbase, pbase+1
    const int pbase = ((lane & 1)  << 5) | ((lane & 2)  << 3) | ((lane & 4) << 1)
                    | ((lane & 8)  >> 1) | ((lane & 16) >> 3);

    const float dot0 = acc[0], dot1 = acc[1];
    const float cos0 = dot0 * rz * __ldg(&g_pnorm_inv[pbase]);
    const float cos1 = dot1 * rz * __ldg(&g_pnorm_inv[pbase + 1]);
    const float dst0 = sqrtf(fmaxf(zn2 + __ldg(&g_pnorm2[pbase])     - 2.0f * dot0, 0.f));
    const float dst1 = sqrtf(fmaxf(zn2 + __ldg(&g_pnorm2[pbase + 1]) - 2.0f * dot1, 0.f));

    g_cos[n * PP + pbase]     = cos0;
    g_cos[n * PP + pbase + 1] = cos1;
    atomicMin(&bmin[pbase],     __float_as_uint(dst0));
    atomicMin(&bmin[pbase + 1], __float_as_uint(dst1));

    // per-sample reductions (pbase<32 iff lane even)
    float minD = fminf(dst0, dst1);
    const float mx = fmaxf(cos0, cos1);
    float mp = (pbase < PPOS) ? mx : -FLT_MAX;
    float mn = (pbase < PPOS) ? -FLT_MAX : mx;
    int cnt = (cos0 > 0.5f) + (cos1 > 0.5f);
#pragma unroll
    for (int o = 16; o; o >>= 1) {
        minD = fminf(minD, __shfl_xor_sync(0xffffffffu, minD, o));
        mp   = fmaxf(mp,   __shfl_xor_sync(0xffffffffu, mp,   o));
        mn   = fmaxf(mn,   __shfl_xor_sync(0xffffffffu, mn,   o));
        cnt += __shfl_xor_sync(0xffffffffu, cnt, o);
    }

    if (lane == 0) {
        atomicAdd(&g_pz_sum, minD);
        const long long lb = labels[n];
        atomicAdd(&g_cl_sum, (lb == 1) ? (1.0f - mp) : (1.0f - mn));
        if (cnt > PP / 4) atomicAdd(&g_num_cnt, 1);
    }
    __syncthreads();
    if (tid < PP) atomicMin(&g_minBits[tid], bmin[tid]);
}

// ---------------------------------------------------------------------------
// K_tokens: token_sequences[n,p,d] = cos[n,p] * proto[p,d]  (268 MB stream)
// ---------------------------------------------------------------------------
__global__ __launch_bounds__(256)
void k_tokens(const float* __restrict__ proto, float* __restrict__ out) {
    const int i  = blockIdx.x * 256 + threadIdx.x;  // float4 index
    const int d4 = i & 63;
    const int p  = (i >> 6) & 63;
    const float c = __ldg(&g_cos[i >> 6]);          // (n*64 + p) == i>>6
    const float4 pr = __ldg((const float4*)proto + p * 64 + d4);
    float4 v = make_float4(c * pr.x, c * pr.y, c * pr.z, c * pr.w);
    ((float4*)out)[i] = v;
}

// ---------------------------------------------------------------------------
// K_final: combine scalar loss terms
// ---------------------------------------------------------------------------
__global__ void k_final(float* __restrict__ out, int loss_idx) {
    __shared__ float s[PP];
    const int t = threadIdx.x;
    if (t < PP) s[t] = __uint_as_float(g_minBits[t]);
    __syncthreads();
    if (t == 0) {
        float zp = 0.f;
#pragma unroll
        for (int k = 0; k < PP; k++) zp += s[k];
        const float l_zp  = zp / (float)PP;
        const float l_pz  = g_pz_sum / (float)NS;
        const float l_pp  = g_pp_sum / (float)(PP * (PP - 1));
        const float l_num = (float)g_num_cnt;
        const float l_cl  = g_cl_sum / (float)NS;
        out[loss_idx] = l_zp + l_pz + l_pp + l_num + l_cl + l_cl;
    }
}

// ---------------------------------------------------------------------------
// kernel_launch
// ---------------------------------------------------------------------------
extern "C" void kernel_launch(void* const* d_in, const int* in_sizes, int n_in,
                              void* d_out, int out_size) {
    const float*     x      = nullptr;
    const long long* labels = nullptr;
    const float*     W      = nullptr;
    const float*     b      = nullptr;
    const float*     proto  = nullptr;
    for (int i = 0; i < n_in; i++) {
        switch (in_sizes[i]) {
            case NS * IND: x      = (const float*)d_in[i];     break;
            case NS:       labels = (const long long*)d_in[i]; break;
            case IND * DD: W      = (const float*)d_in[i];     break;
            case DD:       b      = (const float*)d_in[i];     break;
            case PP * DD:  proto  = (const float*)d_in[i];     break;
        }
    }
    if (!x || !labels || !W || !b || !proto) {
        x      = (const float*)d_in[0];
        labels = (const long long*)d_in[1];
        W      = (const float*)d_in[2];
        b      = (const float*)d_in[3];
        proto  = (const float*)d_in[4];
    }
    float* out = (float*)d_out;

    k_init  <<<1, 64>>>();
    k_proto <<<PP, 256>>>(proto);
    k_gemm  <<<dim3(NS / 128, DD / 128, NSK), 256>>>(x, W, b);
    k_stats <<<NS / 8, 256>>>(proto, labels);
    k_tokens<<<(NS * PP * DD / 4) / 256, 256>>>(proto, out);
    k_final <<<1, 64>>>(out, out_size - 1);
}

// round 3
// speedup vs baseline: 1.2551x; 1.0695x over previous
#include <cuda_runtime.h>
#include <cuda_bf16.h>
#include <math.h>
#include <float.h>

// ---------------------------------------------------------------------------
// Problem constants
// ---------------------------------------------------------------------------
#define NS   4096        // samples
#define IND  768         // input dim
#define DD   256         // prototype dim
#define PP   64          // prototypes
#define PPOS 32          // P/2
#define NSK  4           // split-K factor
#define KCH  (IND / NSK) // 192 (12 tiles of 16)
#define SB   32          // samples per k_stats block

// ---------------------------------------------------------------------------
// Device scratch (static — no runtime allocation allowed)
// ---------------------------------------------------------------------------
__device__ float        g_zpart[NSK][NS][DD]; // split-K partials of z (16 MB)
__device__ float        g_cos[NS * PP];       // cosine similarities (1 MB)
__device__ float        g_pnorm2[PP];
__device__ float        g_pnorm_inv[PP];      // 1 / max(||p||, eps)
__device__ unsigned int g_minBits[PP];        // per-prototype min dist (bits)
__device__ float        g_pp_sum;
__device__ float        g_pz_sum;
__device__ float        g_cl_sum;
__device__ int          g_num_cnt;

__device__ __forceinline__ float warpSum(float v) {
#pragma unroll
    for (int o = 16; o; o >>= 1) v += __shfl_xor_sync(0xffffffffu, v, o);
    return v;
}

// ---------------------------------------------------------------------------
// K_init
// ---------------------------------------------------------------------------
__global__ void k_init() {
    int t = threadIdx.x;
    if (t < PP) g_minBits[t] = 0x7f7fffffu;  // FLT_MAX bits (dists are >= 0)
    if (t == 0) {
        g_pp_sum = 0.f; g_pz_sum = 0.f; g_cl_sum = 0.f; g_num_cnt = 0;
    }
}

// ---------------------------------------------------------------------------
// K_proto: per-prototype norms + pairwise-distance loss (l_pp numerator)
// ---------------------------------------------------------------------------
__global__ void k_proto(const float* __restrict__ proto) {
    const int i = blockIdx.x;
    const int t = threadIdx.x;
    __shared__ float pi[DD];
    __shared__ float red[8];
    __shared__ float ddist[PP];

    float v = proto[i * DD + t];
    pi[t] = v;
    float nrm = warpSum(v * v);
    if ((t & 31) == 0) red[t >> 5] = nrm;
    __syncthreads();
    if (t == 0) {
        float s = 0.f;
#pragma unroll
        for (int w = 0; w < 8; w++) s += red[w];
        g_pnorm2[i]    = s;
        g_pnorm_inv[i] = 1.0f / fmaxf(sqrtf(s), 1e-8f);
    }
    __syncthreads();

    const int j = t >> 2;
    const int q = t & 3;
    const float* pj = proto + j * DD + q * 64;
    float s = 0.f;
#pragma unroll 8
    for (int d = 0; d < 64; d++) {
        float df = pi[q * 64 + d] - pj[d];
        s += df * df;
    }
    s += __shfl_down_sync(0xffffffffu, s, 1);
    s += __shfl_down_sync(0xffffffffu, s, 2);
    if (q == 0) ddist[j] = (j == i) ? 0.f : sqrtf(fmaxf(s, 0.f));
    __syncthreads();
    if (t == 0) {
        float acc = 0.f;
#pragma unroll
        for (int k = 0; k < PP; k++) acc += ddist[k];
        atomicAdd(&g_pp_sum, acc);
    }
}

// ---------------------------------------------------------------------------
// K_gemm: z-partial = x[.,kchunk] @ W[kchunk,.] (+ bias on chunk 0)
// tiles 128x128, K chunk = 192, grid (32, 2, 4) = 256 blocks, 256 threads,
// 8x8/thread, double-buffered smem + register prefetch. (unchanged)
// ---------------------------------------------------------------------------
__global__ __launch_bounds__(256, 2)
void k_gemm(const float* __restrict__ X, const float* __restrict__ W,
            const float* __restrict__ bias) {
    __shared__ float As[2][16][132];   // [buf][k][m], padded
    __shared__ float Bs[2][16][128];   // [buf][k][n]

    const int m0 = blockIdx.x * 128;
    const int n0 = blockIdx.y * 128;
    const int kc = blockIdx.z;
    const int k0 = kc * KCH;

    const int tid = threadIdx.x;
    const int tx = tid & 15, ty = tid >> 4;

    const int arow = tid >> 2;
    const int acol = (tid & 3) * 4;
    const int brow = tid >> 5;
    const int bcol = (tid & 31) * 4;

    float4 ra0, ra1, rb0, rb1;

    {
        const int kk = k0;
        ra0 = *(const float4*)&X[(size_t)(m0 + arow)      * IND + kk + acol];
        ra1 = *(const float4*)&X[(size_t)(m0 + arow + 64) * IND + kk + acol];
        rb0 = *(const float4*)&W[(size_t)(kk + brow)     * DD + n0 + bcol];
        rb1 = *(const float4*)&W[(size_t)(kk + brow + 8) * DD + n0 + bcol];
    }
    As[0][acol + 0][arow]      = ra0.x;
    As[0][acol + 1][arow]      = ra0.y;
    As[0][acol + 2][arow]      = ra0.z;
    As[0][acol + 3][arow]      = ra0.w;
    As[0][acol + 0][arow + 64] = ra1.x;
    As[0][acol + 1][arow + 64] = ra1.y;
    As[0][acol + 2][arow + 64] = ra1.z;
    As[0][acol + 3][arow + 64] = ra1.w;
    *(float4*)&Bs[0][brow][bcol]     = rb0;
    *(float4*)&Bs[0][brow + 8][bcol] = rb1;
    __syncthreads();

    float acc[8][8];
#pragma unroll
    for (int i = 0; i < 8; i++)
#pragma unroll
        for (int j = 0; j < 8; j++) acc[i][j] = 0.f;

    const int NT = KCH / 16;  // 12
#pragma unroll 2
    for (int t = 0; t < NT; t++) {
        const int buf = t & 1;
        const bool more = (t + 1 < NT);
        if (more) {
            const int kk = k0 + (t + 1) * 16;
            ra0 = *(const float4*)&X[(size_t)(m0 + arow)      * IND + kk + acol];
            ra1 = *(const float4*)&X[(size_t)(m0 + arow + 64) * IND + kk + acol];
            rb0 = *(const float4*)&W[(size_t)(kk + brow)     * DD + n0 + bcol];
            rb1 = *(const float4*)&W[(size_t)(kk + brow + 8) * DD + n0 + bcol];
        }
#pragma unroll
        for (int kk = 0; kk < 16; kk++) {
            float a[8], b[8];
            *(float4*)&a[0] = *(const float4*)&As[buf][kk][ty * 8];
            *(float4*)&a[4] = *(const float4*)&As[buf][kk][ty * 8 + 4];
            *(float4*)&b[0] = *(const float4*)&Bs[buf][kk][tx * 8];
            *(float4*)&b[4] = *(const float4*)&Bs[buf][kk][tx * 8 + 4];
#pragma unroll
            for (int i = 0; i < 8; i++)
#pragma unroll
                for (int j = 0; j < 8; j++) acc[i][j] += a[i] * b[j];
        }
        if (more) {
            const int nb = buf ^ 1;
            As[nb][acol + 0][arow]      = ra0.x;
            As[nb][acol + 1][arow]      = ra0.y;
            As[nb][acol + 2][arow]      = ra0.z;
            As[nb][acol + 3][arow]      = ra0.w;
            As[nb][acol + 0][arow + 64] = ra1.x;
            As[nb][acol + 1][arow + 64] = ra1.y;
            As[nb][acol + 2][arow + 64] = ra1.z;
            As[nb][acol + 3][arow + 64] = ra1.w;
            *(float4*)&Bs[nb][brow][bcol]     = rb0;
            *(float4*)&Bs[nb][brow + 8][bcol] = rb1;
        }
        __syncthreads();
    }

    float bj[8];
#pragma unroll
    for (int j = 0; j < 8; j++)
        bj[j] = (kc == 0) ? bias[n0 + tx * 8 + j] : 0.f;

    float* zc = &g_zpart[kc][0][0];
#pragma unroll
    for (int i = 0; i < 8; i++) {
        const int m = m0 + ty * 8 + i;
        float* orow = zc + (size_t)m * DD + n0 + tx * 8;
        float4 v0 = make_float4(acc[i][0] + bj[0], acc[i][1] + bj[1],
                                acc[i][2] + bj[2], acc[i][3] + bj[3]);
        float4 v1 = make_float4(acc[i][4] + bj[4], acc[i][5] + bj[5],
                                acc[i][6] + bj[6], acc[i][7] + bj[7]);
        *(float4*)&orow[0] = v0;
        *(float4*)&orow[4] = v1;
    }
}

// ---------------------------------------------------------------------------
// K_stats v3: smem-tiled mini-GEMM dot[32s x 64p] per block.
// grid = 128 blocks x 256 threads. Prototypes staged once per block
// (transposed, chunked over d). Thread computes 2 samples x 4 protos.
// ---------------------------------------------------------------------------
__global__ __launch_bounds__(256, 2)
void k_stats(const float* __restrict__ proto, const long long* __restrict__ labels) {
    __shared__ __align__(16) float pT[64][68];   // proto chunk, transposed [d][p]
    __shared__ float zsT[64][33];                // z chunk, transposed [d][s]
    __shared__ float s_zn2[SB];
    __shared__ unsigned int bmin[PP];
    __shared__ float s_pz, s_cl;
    __shared__ int   s_cnt;

    const int tid  = threadIdx.x;
    const int lane = tid & 31;
    const int n0   = blockIdx.x * SB;

    // dot-compute mapping: pg in [0,16), sA in [0,16), sB = sA+16
    const int pg = tid & 15;
    const int sA = tid >> 4;
    const int sB = sA + 16;
    const int p0 = pg * 4;

    // init shared accumulators
    if (tid < PP) bmin[tid] = 0x7f7fffffu;
    if (tid < SB) s_zn2[tid] = 0.f;
    if (tid == 0) { s_pz = 0.f; s_cl = 0.f; s_cnt = 0; }

    float accA[4] = {0.f, 0.f, 0.f, 0.f};
    float accB[4] = {0.f, 0.f, 0.f, 0.f};
    float zn2p = 0.f;
    const int zS = tid & 31;      // zn2 mapping: sample
    const int zG = tid >> 5;      // zn2 mapping: d-group (8 d's per chunk)

#pragma unroll 1
    for (int ch = 0; ch < 4; ch++) {
        __syncthreads();  // protect previous chunk's reads (and the init)

        // stage zsT: 32 s x 64 d, summing NSK split-K partials
#pragma unroll
        for (int i = 0; i < 2; i++) {
            const int idx = tid * 2 + i;          // 0..511
            const int s  = idx >> 4;              // 0..31
            const int d  = (idx & 15) * 4;        // 0..60
            const float* zp = &g_zpart[0][0][0] + (size_t)(n0 + s) * DD + ch * 64 + d;
            float4 v = *(const float4*)(zp);
#pragma unroll
            for (int c = 1; c < NSK; c++) {
                const float4 u = *(const float4*)(zp + (size_t)c * NS * DD);
                v.x += u.x; v.y += u.y; v.z += u.z; v.w += u.w;
            }
            zsT[d + 0][s] = v.x;
            zsT[d + 1][s] = v.y;
            zsT[d + 2][s] = v.z;
            zsT[d + 3][s] = v.w;
        }
        // stage pT: 64 p x 64 d, transposed
#pragma unroll
        for (int i = 0; i < 4; i++) {
            const int idx = i * 256 + tid;        // 0..1023
            const int p  = idx >> 4;              // 0..63
            const int d  = (idx & 15) * 4;
            const float4 v = __ldg((const float4*)&proto[p * DD + ch * 64 + d]);
            pT[d + 0][p] = v.x;
            pT[d + 1][p] = v.y;
            pT[d + 2][p] = v.z;
            pT[d + 3][p] = v.w;
        }
        __syncthreads();

        // zn2 partial (thread: sample zS, d-group zG)
#pragma unroll
        for (int j = 0; j < 8; j++) {
            const float v = zsT[zG * 8 + j][zS];
            zn2p += v * v;
        }

        // dot FMAs: 2 samples x 4 protos over 64 d
#pragma unroll 4
        for (int d = 0; d < 64; d++) {
            const float4 pv = *(const float4*)&pT[d][p0];
            const float za = zsT[d][sA];
            const float zb = zsT[d][sB];
            accA[0] += za * pv.x; accA[1] += za * pv.y;
            accA[2] += za * pv.z; accA[3] += za * pv.w;
            accB[0] += zb * pv.x; accB[1] += zb * pv.y;
            accB[2] += zb * pv.z; accB[3] += zb * pv.w;
        }
    }

    atomicAdd(&s_zn2[zS], zn2p);
    __syncthreads();

    const float zn2A = s_zn2[sA];
    const float zn2B = s_zn2[sB];
    const float rzA = 1.0f / fmaxf(sqrtf(zn2A), 1e-8f);
    const float rzB = 1.0f / fmaxf(sqrtf(zn2B), 1e-8f);

    const float4 pinv = __ldg((const float4*)&g_pnorm_inv[p0]);
    const float4 pn2  = __ldg((const float4*)&g_pnorm2[p0]);

    float cosA[4], cosB[4], dstA[4], dstB[4];
    const float pinvs[4] = {pinv.x, pinv.y, pinv.z, pinv.w};
    const float pn2s[4]  = {pn2.x,  pn2.y,  pn2.z,  pn2.w};
#pragma unroll
    for (int j = 0; j < 4; j++) {
        cosA[j] = accA[j] * rzA * pinvs[j];
        cosB[j] = accB[j] * rzB * pinvs[j];
        dstA[j] = sqrtf(fmaxf(zn2A + pn2s[j] - 2.0f * accA[j], 0.f));
        dstB[j] = sqrtf(fmaxf(zn2B + pn2s[j] - 2.0f * accB[j], 0.f));
    }

    // write cosine rows (float4, aligned)
    *(float4*)&g_cos[(size_t)(n0 + sA) * PP + p0] =
        make_float4(cosA[0], cosA[1], cosA[2], cosA[3]);
    *(float4*)&g_cos[(size_t)(n0 + sB) * PP + p0] =
        make_float4(cosB[0], cosB[1], cosB[2], cosB[3]);

    // per-prototype min distance: pre-reduce over the warp's 2x2 samples
#pragma unroll
    for (int j = 0; j < 4; j++) {
        float mj = fminf(dstA[j], dstB[j]);
        mj = fminf(mj, __shfl_xor_sync(0xffffffffu, mj, 16));
        if (lane < 16) atomicMin(&bmin[p0 + j], __float_as_uint(mj));
    }

    // per-sample reductions across the 16 pg threads
    float minDA = fminf(fminf(dstA[0], dstA[1]), fminf(dstA[2], dstA[3]));
    float minDB = fminf(fminf(dstB[0], dstB[1]), fminf(dstB[2], dstB[3]));
    const float mxA = fmaxf(fmaxf(cosA[0], cosA[1]), fmaxf(cosA[2], cosA[3]));
    const float mxB = fmaxf(fmaxf(cosB[0], cosB[1]), fmaxf(cosB[2], cosB[3]));
    const bool pos = (pg < 8);   // p0..p0+3 all < 32 iff pg < 8
    float mpA = pos ? mxA : -FLT_MAX, mnA = pos ? -FLT_MAX : mxA;
    float mpB = pos ? mxB : -FLT_MAX, mnB = pos ? -FLT_MAX : mxB;
    int cntA = (cosA[0] > 0.5f) + (cosA[1] > 0.5f) + (cosA[2] > 0.5f) + (cosA[3] > 0.5f);
    int cntB = (cosB[0] > 0.5f) + (cosB[1] > 0.5f) + (cosB[2] > 0.5f) + (cosB[3] > 0.5f);
#pragma unroll
    for (int o = 1; o < 16; o <<= 1) {
        minDA = fminf(minDA, __shfl_xor_sync(0xffffffffu, minDA, o));
        minDB = fminf(minDB, __shfl_xor_sync(0xffffffffu, minDB, o));
        mpA   = fmaxf(mpA,   __shfl_xor_sync(0xffffffffu, mpA,   o));
        mpB   = fmaxf(mpB,   __shfl_xor_sync(0xffffffffu, mpB,   o));
        mnA   = fmaxf(mnA,   __shfl_xor_sync(0xffffffffu, mnA,   o));
        mnB   = fmaxf(mnB,   __shfl_xor_sync(0xffffffffu, mnB,   o));
        cntA += __shfl_xor_sync(0xffffffffu, cntA, o);
        cntB += __shfl_xor_sync(0xffffffffu, cntB, o);
    }
    if (pg == 0) {
        const long long lbA = labels[n0 + sA];
        const long long lbB = labels[n0 + sB];
        atomicAdd(&s_pz, minDA + minDB);
        atomicAdd(&s_cl, ((lbA == 1) ? (1.0f - mpA) : (1.0f - mnA))
                       + ((lbB == 1) ? (1.0f - mpB) : (1.0f - mnB)));
        atomicAdd(&s_cnt, (cntA > PP / 4 ? 1 : 0) + (cntB > PP / 4 ? 1 : 0));
    }
    __syncthreads();

    // one global update per block
    if (tid == 0) {
        atomicAdd(&g_pz_sum, s_pz);
        atomicAdd(&g_cl_sum, s_cl);
        if (s_cnt) atomicAdd(&g_num_cnt, s_cnt);
    }
    if (tid < PP) atomicMin(&g_minBits[tid], bmin[tid]);
}

// ---------------------------------------------------------------------------
// K_tokens: token_sequences[n,p,d] = cos[n,p] * proto[p,d]  (268 MB stream)
// ---------------------------------------------------------------------------
__global__ __launch_bounds__(256)
void k_tokens(const float* __restrict__ proto, float* __restrict__ out) {
    const int i  = blockIdx.x * 256 + threadIdx.x;  // float4 index
    const int d4 = i & 63;
    const int p  = (i >> 6) & 63;
    const float c = __ldg(&g_cos[i >> 6]);          // (n*64 + p) == i>>6
    const float4 pr = __ldg((const float4*)proto + p * 64 + d4);
    float4 v = make_float4(c * pr.x, c * pr.y, c * pr.z, c * pr.w);
    ((float4*)out)[i] = v;
}

// ---------------------------------------------------------------------------
// K_final: combine scalar loss terms
// ---------------------------------------------------------------------------
__global__ void k_final(float* __restrict__ out, int loss_idx) {
    __shared__ float s[PP];
    const int t = threadIdx.x;
    if (t < PP) s[t] = __uint_as_float(g_minBits[t]);
    __syncthreads();
    if (t == 0) {
        float zp = 0.f;
#pragma unroll
        for (int k = 0; k < PP; k++) zp += s[k];
        const float l_zp  = zp / (float)PP;
        const float l_pz  = g_pz_sum / (float)NS;
        const float l_pp  = g_pp_sum / (float)(PP * (PP - 1));
        const float l_num = (float)g_num_cnt;
        const float l_cl  = g_cl_sum / (float)NS;
        out[loss_idx] = l_zp + l_pz + l_pp + l_num + l_cl + l_cl;
    }
}

// ---------------------------------------------------------------------------
// kernel_launch
// ---------------------------------------------------------------------------
extern "C" void kernel_launch(void* const* d_in, const int* in_sizes, int n_in,
                              void* d_out, int out_size) {
    const float*     x      = nullptr;
    const long long* labels = nullptr;
    const float*     W      = nullptr;
    const float*     b      = nullptr;
    const float*     proto  = nullptr;
    for (int i = 0; i < n_in; i++) {
        switch (in_sizes[i]) {
            case NS * IND: x      = (const float*)d_in[i];     break;
            case NS:       labels = (const long long*)d_in[i]; break;
            case IND * DD: W      = (const float*)d_in[i];     break;
            case DD:       b      = (const float*)d_in[i];     break;
            case PP * DD:  proto  = (const float*)d_in[i];     break;
        }
    }
    if (!x || !labels || !W || !b || !proto) {
        x      = (const float*)d_in[0];
        labels = (const long long*)d_in[1];
        W      = (const float*)d_in[2];
        b      = (const float*)d_in[3];
        proto  = (const float*)d_in[4];
    }
    float* out = (float*)d_out;

    k_init  <<<1, 64>>>();
    k_proto <<<PP, 256>>>(proto);
    k_gemm  <<<dim3(NS / 128, DD / 128, NSK), 256>>>(x, W, b);
    k_stats <<<NS / SB, 256>>>(proto, labels);
    k_tokens<<<(NS * PP * DD / 4) / 256, 256>>>(proto, out);
    k_final <<<1, 64>>>(out, out_size - 1);
}

// round 5
// speedup vs baseline: 1.3228x; 1.0539x over previous
#include <cuda_runtime.h>
#include <cuda_bf16.h>
#include <math.h>
#include <float.h>
#include <stdint.h>

// ---------------------------------------------------------------------------
// Problem constants
// ---------------------------------------------------------------------------
#define NS   4096        // samples
#define IND  768         // input dim
#define DD   256         // prototype dim
#define PP   64          // prototypes
#define PPOS 32          // P/2
#define SB   16          // samples per k_stats block

// ---------------------------------------------------------------------------
// Device scratch (static — no runtime allocation allowed)
// ---------------------------------------------------------------------------
__device__ float          g_z[NS * DD];          // z = xW+b (4 MB, written once)
__device__ __nv_bfloat16  g_xhi[NS * IND];       // x hi bf16, [M][K]
__device__ __nv_bfloat16  g_xlo[NS * IND];       // x lo bf16
__device__ __nv_bfloat16  g_bhi[DD * IND];       // W^T hi, [N][K]
__device__ __nv_bfloat16  g_blo[DD * IND];       // W^T lo
__device__ float          g_cos[NS * PP];        // cosine similarities (1 MB)
__device__ float          g_pnorm2[PP];
__device__ float          g_pnorm_inv[PP];
__device__ unsigned int   g_minBits[PP];
__device__ float          g_pp_sum;
__device__ float          g_pz_sum;
__device__ float          g_cl_sum;
__device__ int            g_num_cnt;

__device__ __forceinline__ float warpSum(float v) {
#pragma unroll
    for (int o = 16; o; o >>= 1) v += __shfl_xor_sync(0xffffffffu, v, o);
    return v;
}

__device__ __forceinline__ uint32_t smem_u32(const void* p) {
    uint32_t a;
    asm("{ .reg .u64 t; cvta.to.shared.u64 t, %1; cvt.u32.u64 %0, t; }"
        : "=r"(a) : "l"(p));
    return a;
}

__device__ __forceinline__ void cp16(uint32_t sdst, const void* gsrc) {
    asm volatile("cp.async.cg.shared.global [%0], [%1], 16;"
                 :: "r"(sdst), "l"(gsrc) : "memory");
}

// m16n8k16 row.col f32.bf16.bf16.f32
__device__ __forceinline__ void mma16816(float (&d)[4], const uint32_t (&a)[4],
                                         const uint32_t (&b)[2]) {
    asm volatile(
        "mma.sync.aligned.m16n8k16.row.col.f32.bf16.bf16.f32 "
        "{%0,%1,%2,%3}, {%4,%5,%6,%7}, {%8,%9}, {%0,%1,%2,%3};"
        : "+f"(d[0]), "+f"(d[1]), "+f"(d[2]), "+f"(d[3])
        : "r"(a[0]), "r"(a[1]), "r"(a[2]), "r"(a[3]),
          "r"(b[0]), "r"(b[1]));
}

// GEMM smem layout: bf16 tiles, padded stride 72 bf16 (144 B) for conflict-free
// b32 fragment loads (row step = 36 banks -> 8 rows cover 8 distinct 4-bank groups)
#define ASTR     72
#define OFF_AHI  0
#define OFF_ALO  18432            // 128*72*2
#define OFF_BHI  36864
#define OFF_BLO  46080            // +64*72*2
#define GBUF     55296
#define SMEM_GEMM (2 * GBUF)      // 110592 B

// ---------------------------------------------------------------------------
// K_init
// ---------------------------------------------------------------------------
__global__ void k_init() {
    int t = threadIdx.x;
    if (t < PP) g_minBits[t] = 0x7f7fffffu;
    if (t == 0) { g_pp_sum = 0.f; g_pz_sum = 0.f; g_cl_sum = 0.f; g_num_cnt = 0; }
}

// ---------------------------------------------------------------------------
// K_proto: per-prototype norms + pairwise-distance loss
// ---------------------------------------------------------------------------
__global__ void k_proto(const float* __restrict__ proto) {
    const int i = blockIdx.x;
    const int t = threadIdx.x;
    __shared__ float pi[DD];
    __shared__ float red[8];
    __shared__ float ddist[PP];

    float v = proto[i * DD + t];
    pi[t] = v;
    float nrm = warpSum(v * v);
    if ((t & 31) == 0) red[t >> 5] = nrm;
    __syncthreads();
    if (t == 0) {
        float s = 0.f;
#pragma unroll
        for (int w = 0; w < 8; w++) s += red[w];
        g_pnorm2[i]    = s;
        g_pnorm_inv[i] = 1.0f / fmaxf(sqrtf(s), 1e-8f);
    }
    __syncthreads();

    const int j = t >> 2;
    const int q = t & 3;
    const float* pj = proto + j * DD + q * 64;
    float s = 0.f;
#pragma unroll 8
    for (int d = 0; d < 64; d++) {
        float df = pi[q * 64 + d] - pj[d];
        s += df * df;
    }
    s += __shfl_down_sync(0xffffffffu, s, 1);
    s += __shfl_down_sync(0xffffffffu, s, 2);
    if (q == 0) ddist[j] = (j == i) ? 0.f : sqrtf(fmaxf(s, 0.f));
    __syncthreads();
    if (t == 0) {
        float acc = 0.f;
#pragma unroll
        for (int k = 0; k < PP; k++) acc += ddist[k];
        atomicAdd(&g_pp_sum, acc);
    }
}

// ---------------------------------------------------------------------------
// K_convX: split x into hi/lo bf16 (same [M][K] layout, linear copy)
// ---------------------------------------------------------------------------
__global__ __launch_bounds__(256)
void k_convX(const float* __restrict__ X) {
    const int i = blockIdx.x * 256 + threadIdx.x;       // float4 index
    const float4 v = ((const float4*)X)[i];
    const __nv_bfloat16 h0 = __float2bfloat16_rn(v.x);
    const __nv_bfloat16 h1 = __float2bfloat16_rn(v.y);
    const __nv_bfloat16 h2 = __float2bfloat16_rn(v.z);
    const __nv_bfloat16 h3 = __float2bfloat16_rn(v.w);
    const __nv_bfloat16 l0 = __float2bfloat16_rn(v.x - __bfloat162float(h0));
    const __nv_bfloat16 l1 = __float2bfloat16_rn(v.y - __bfloat162float(h1));
    const __nv_bfloat16 l2 = __float2bfloat16_rn(v.z - __bfloat162float(h2));
    const __nv_bfloat16 l3 = __float2bfloat16_rn(v.w - __bfloat162float(h3));
    const uint32_t hp0 = ((uint32_t)__bfloat16_as_ushort(h1) << 16) | __bfloat16_as_ushort(h0);
    const uint32_t hp1 = ((uint32_t)__bfloat16_as_ushort(h3) << 16) | __bfloat16_as_ushort(h2);
    const uint32_t lp0 = ((uint32_t)__bfloat16_as_ushort(l1) << 16) | __bfloat16_as_ushort(l0);
    const uint32_t lp1 = ((uint32_t)__bfloat16_as_ushort(l3) << 16) | __bfloat16_as_ushort(l2);
    ((uint2*)g_xhi)[i] = make_uint2(hp0, hp1);
    ((uint2*)g_xlo)[i] = make_uint2(lp0, lp1);
}

// ---------------------------------------------------------------------------
// K_convW: split W into hi/lo bf16, transposed to [N][K]
// ---------------------------------------------------------------------------
__global__ __launch_bounds__(256)
void k_convW(const float* __restrict__ W) {
    const int idx = blockIdx.x * 256 + threadIdx.x;   // 196608 total
    const int n = idx & 255;
    const int k = idx >> 8;
    const float w = W[(size_t)k * DD + n];            // coalesced read
    const __nv_bfloat16 h = __float2bfloat16_rn(w);
    const __nv_bfloat16 l = __float2bfloat16_rn(w - __bfloat162float(h));
    g_bhi[(size_t)n * IND + k] = h;
    g_blo[(size_t)n * IND + k] = l;
}

// ---------------------------------------------------------------------------
// K_gemm_hmma: z = x @ W + b via mma.sync bf16x3 (hi*hi + hi*lo + lo*hi).
// CTA tile 128x64, full K=768 in 12 chunks of 64, cp.async double-buffered.
// grid (32, 4) = 128 blocks, 256 threads (8 warps, warp tile 32x32).
// ---------------------------------------------------------------------------
__global__ __launch_bounds__(256, 1)
void k_gemm_hmma(const float* __restrict__ bias) {
    extern __shared__ __align__(128) char sm[];
    const uint32_t smb = smem_u32(sm);

    const int tid  = threadIdx.x;
    const int wid  = tid >> 5;
    const int lane = tid & 31;
    const int gid  = lane >> 2;    // group id 0..7
    const int tig  = lane & 3;     // thread in group
    const int m0   = blockIdx.x * 128;
    const int n0   = blockIdx.y * 64;
    const int wm   = (wid & 3) * 32;   // warp m-offset within tile
    const int wn   = (wid >> 2) * 32;  // warp n-offset within tile

    // ---- staging (cp.async), one chunk = 64 k ----
    auto stage = [&](int buf, int c) {
        const uint32_t bb = smb + buf * GBUF;
        const int k0 = c * 64;
#pragma unroll
        for (int i = 0; i < 4; i++) {
            const int idx = i * 256 + tid;          // 0..1023
            const int r = idx >> 3, c8 = idx & 7;
            const size_t g = (size_t)(m0 + r) * IND + k0 + c8 * 8;
            const uint32_t d = bb + OFF_AHI + (uint32_t)(r * ASTR + c8 * 8) * 2;
            cp16(d,                      g_xhi + g);
            cp16(d + (OFF_ALO - OFF_AHI), g_xlo + g);
        }
#pragma unroll
        for (int i = 0; i < 2; i++) {
            const int idx = i * 256 + tid;          // 0..511
            const int r = idx >> 3, c8 = idx & 7;
            const size_t g = (size_t)(n0 + r) * IND + k0 + c8 * 8;
            const uint32_t d = bb + OFF_BHI + (uint32_t)(r * ASTR + c8 * 8) * 2;
            cp16(d,                      g_bhi + g);
            cp16(d + (OFF_BLO - OFF_BHI), g_blo + g);
        }
        asm volatile("cp.async.commit_group;" ::: "memory");
    };

    float acc[2][4][4];
#pragma unroll
    for (int mt = 0; mt < 2; mt++)
#pragma unroll
        for (int nt = 0; nt < 4; nt++)
#pragma unroll
            for (int q = 0; q < 4; q++) acc[mt][nt][q] = 0.f;

    stage(0, 0);

#pragma unroll 1
    for (int c = 0; c < 12; c++) {
        const int buf = c & 1;
        if (c < 11) {
            stage(buf ^ 1, c + 1);
            asm volatile("cp.async.wait_group 1;" ::: "memory");
        } else {
            asm volatile("cp.async.wait_group 0;" ::: "memory");
        }
        __syncthreads();

        const char* bb = sm + buf * GBUF;
#pragma unroll
        for (int ks = 0; ks < 4; ks++) {
            const int kk = ks * 16;
            uint32_t Ahif[2][4], Alof[2][4];
#pragma unroll
            for (int mt = 0; mt < 2; mt++) {
                const int row = wm + mt * 16 + gid;
                const char* pa = bb + OFF_AHI + (uint32_t)(row * ASTR + kk + tig * 2) * 2;
                Ahif[mt][0] = *(const uint32_t*)(pa);
                Ahif[mt][1] = *(const uint32_t*)(pa + 8 * ASTR * 2);
                Ahif[mt][2] = *(const uint32_t*)(pa + 16);
                Ahif[mt][3] = *(const uint32_t*)(pa + 8 * ASTR * 2 + 16);
                const char* pl = pa + (OFF_ALO - OFF_AHI);
                Alof[mt][0] = *(const uint32_t*)(pl);
                Alof[mt][1] = *(const uint32_t*)(pl + 8 * ASTR * 2);
                Alof[mt][2] = *(const uint32_t*)(pl + 16);
                Alof[mt][3] = *(const uint32_t*)(pl + 8 * ASTR * 2 + 16);
            }
            uint32_t Bhif[4][2], Blof[4][2];
#pragma unroll
            for (int nt = 0; nt < 4; nt++) {
                const int row = wn + nt * 8 + gid;
                const char* pb = bb + OFF_BHI + (uint32_t)(row * ASTR + kk + tig * 2) * 2;
                Bhif[nt][0] = *(const uint32_t*)(pb);
                Bhif[nt][1] = *(const uint32_t*)(pb + 16);
                const char* pl = pb + (OFF_BLO - OFF_BHI);
                Blof[nt][0] = *(const uint32_t*)(pl);
                Blof[nt][1] = *(const uint32_t*)(pl + 16);
            }
#pragma unroll
            for (int mt = 0; mt < 2; mt++)
#pragma unroll
                for (int nt = 0; nt < 4; nt++) {
                    mma16816(acc[mt][nt], Ahif[mt], Bhif[nt]);
                    mma16816(acc[mt][nt], Ahif[mt], Blof[nt]);
                    mma16816(acc[mt][nt], Alof[mt], Bhif[nt]);
                }
        }
        __syncthreads();
    }

    // ---- epilogue: + bias, write z ----
#pragma unroll
    for (int nt = 0; nt < 4; nt++) {
        const int col = n0 + wn + nt * 8 + tig * 2;
        const float2 bv = *(const float2*)&bias[col];
#pragma unroll
        for (int mt = 0; mt < 2; mt++) {
            const int row = m0 + wm + mt * 16 + gid;
            float2 v0 = make_float2(acc[mt][nt][0] + bv.x, acc[mt][nt][1] + bv.y);
            float2 v1 = make_float2(acc[mt][nt][2] + bv.x, acc[mt][nt][3] + bv.y);
            *(float2*)&g_z[(size_t)row * DD + col]       = v0;
            *(float2*)&g_z[(size_t)(row + 8) * DD + col] = v1;
        }
    }
}

// ---------------------------------------------------------------------------
// K_stats: smem-tiled dot[16s x 64p] per block, grid = 256.
// ---------------------------------------------------------------------------
__global__ __launch_bounds__(256)
void k_stats(const float* __restrict__ proto, const long long* __restrict__ labels) {
    __shared__ __align__(16) float pT[64][68];   // proto chunk transposed [d][p]
    __shared__ float zsT[64][17];                // z chunk transposed [d][s]
    __shared__ unsigned int bmin[PP];
    __shared__ float s_pz, s_cl;
    __shared__ int   s_cnt;

    const int tid = threadIdx.x;
    const int n0  = blockIdx.x * SB;
    const int s   = tid >> 4;       // 0..15 sample
    const int pg  = tid & 15;       // 0..15 proto group
    const int p0  = pg * 4;

    if (tid < PP) bmin[tid] = 0x7f7fffffu;
    if (tid == 0) { s_pz = 0.f; s_cl = 0.f; s_cnt = 0; }

    float acc[4] = {0.f, 0.f, 0.f, 0.f};
    float zn2p = 0.f;

#pragma unroll 1
    for (int ch = 0; ch < 4; ch++) {
        __syncthreads();
        {
            const float4 v = *(const float4*)&g_z[(size_t)(n0 + s) * DD + ch * 64 + pg * 4];
            zsT[pg * 4 + 0][s] = v.x;
            zsT[pg * 4 + 1][s] = v.y;
            zsT[pg * 4 + 2][s] = v.z;
            zsT[pg * 4 + 3][s] = v.w;
        }
#pragma unroll
        for (int i = 0; i < 4; i++) {
            const int idx = i * 256 + tid;
            const int p  = idx >> 4;
            const int d  = (idx & 15) * 4;
            const float4 v = __ldg((const float4*)&proto[p * DD + ch * 64 + d]);
            pT[d + 0][p] = v.x;
            pT[d + 1][p] = v.y;
            pT[d + 2][p] = v.z;
            pT[d + 3][p] = v.w;
        }
        __syncthreads();

#pragma unroll
        for (int j = 0; j < 4; j++) {
            const float v = zsT[pg * 4 + j][s];
            zn2p += v * v;
        }
#pragma unroll 4
        for (int d = 0; d < 64; d++) {
            const float4 pv = *(const float4*)&pT[d][p0];
            const float zv = zsT[d][s];
            acc[0] += zv * pv.x; acc[1] += zv * pv.y;
            acc[2] += zv * pv.z; acc[3] += zv * pv.w;
        }
    }

#pragma unroll
    for (int o = 1; o < 16; o <<= 1) zn2p += __shfl_xor_sync(0xffffffffu, zn2p, o);
    const float zn2 = zn2p;
    const float rz  = 1.0f / fmaxf(sqrtf(zn2), 1e-8f);

    const float4 pinv = __ldg((const float4*)&g_pnorm_inv[p0]);
    const float4 pn2  = __ldg((const float4*)&g_pnorm2[p0]);
    const float pinvs[4] = {pinv.x, pinv.y, pinv.z, pinv.w};
    const float pn2s[4]  = {pn2.x,  pn2.y,  pn2.z,  pn2.w};

    float cosv[4], dstv[4];
#pragma unroll
    for (int j = 0; j < 4; j++) {
        cosv[j] = acc[j] * rz * pinvs[j];
        dstv[j] = sqrtf(fmaxf(zn2 + pn2s[j] - 2.0f * acc[j], 0.f));
    }
    *(float4*)&g_cos[(size_t)(n0 + s) * PP + p0] =
        make_float4(cosv[0], cosv[1], cosv[2], cosv[3]);

#pragma unroll
    for (int j = 0; j < 4; j++)
        atomicMin(&bmin[p0 + j], __float_as_uint(dstv[j]));

    float minD = fminf(fminf(dstv[0], dstv[1]), fminf(dstv[2], dstv[3]));
    const float mx = fmaxf(fmaxf(cosv[0], cosv[1]), fmaxf(cosv[2], cosv[3]));
    const bool pos = (pg < 8);
    float mp = pos ? mx : -FLT_MAX;
    float mn = pos ? -FLT_MAX : mx;
    int cnt = (cosv[0] > 0.5f) + (cosv[1] > 0.5f) + (cosv[2] > 0.5f) + (cosv[3] > 0.5f);
#pragma unroll
    for (int o = 1; o < 16; o <<= 1) {
        minD = fminf(minD, __shfl_xor_sync(0xffffffffu, minD, o));
        mp   = fmaxf(mp,   __shfl_xor_sync(0xffffffffu, mp,   o));
        mn   = fmaxf(mn,   __shfl_xor_sync(0xffffffffu, mn,   o));
        cnt += __shfl_xor_sync(0xffffffffu, cnt, o);
    }
    if (pg == 0) {
        const long long lb = labels[n0 + s];
        atomicAdd(&s_pz, minD);
        atomicAdd(&s_cl, (lb == 1) ? (1.0f - mp) : (1.0f - mn));
        if (cnt > PP / 4) atomicAdd(&s_cnt, 1);
    }
    __syncthreads();

    if (tid == 0) {
        atomicAdd(&g_pz_sum, s_pz);
        atomicAdd(&g_cl_sum, s_cl);
        if (s_cnt) atomicAdd(&g_num_cnt, s_cnt);
    }
    if (tid < PP) atomicMin(&g_minBits[tid], bmin[tid]);
}

// ---------------------------------------------------------------------------
// K_tokens: token_sequences[n,p,d] = cos[n,p] * proto[p,d]  (268 MB stream)
// ---------------------------------------------------------------------------
__global__ __launch_bounds__(256)
void k_tokens(const float* __restrict__ proto, float* __restrict__ out) {
    const int i  = blockIdx.x * 256 + threadIdx.x;  // float4 index
    const int d4 = i & 63;
    const int p  = (i >> 6) & 63;
    const float c = __ldg(&g_cos[i >> 6]);
    const float4 pr = __ldg((const float4*)proto + p * 64 + d4);
    ((float4*)out)[i] = make_float4(c * pr.x, c * pr.y, c * pr.z, c * pr.w);
}

// ---------------------------------------------------------------------------
// K_final
// ---------------------------------------------------------------------------
__global__ void k_final(float* __restrict__ out, int loss_idx) {
    __shared__ float s[PP];
    const int t = threadIdx.x;
    if (t < PP) s[t] = __uint_as_float(g_minBits[t]);
    __syncthreads();
    if (t == 0) {
        float zp = 0.f;
#pragma unroll
        for (int k = 0; k < PP; k++) zp += s[k];
        const float l_zp  = zp / (float)PP;
        const float l_pz  = g_pz_sum / (float)NS;
        const float l_pp  = g_pp_sum / (float)(PP * (PP - 1));
        const float l_num = (float)g_num_cnt;
        const float l_cl  = g_cl_sum / (float)NS;
        out[loss_idx] = l_zp + l_pz + l_pp + l_num + l_cl + l_cl;
    }
}

// ---------------------------------------------------------------------------
// kernel_launch
// ---------------------------------------------------------------------------
extern "C" void kernel_launch(void* const* d_in, const int* in_sizes, int n_in,
                              void* d_out, int out_size) {
    const float*     x      = nullptr;
    const long long* labels = nullptr;
    const float*     W      = nullptr;
    const float*     b      = nullptr;
    const float*     proto  = nullptr;
    for (int i = 0; i < n_in; i++) {
        switch (in_sizes[i]) {
            case NS * IND: x      = (const float*)d_in[i];     break;
            case NS:       labels = (const long long*)d_in[i]; break;
            case IND * DD: W      = (const float*)d_in[i];     break;
            case DD:       b      = (const float*)d_in[i];     break;
            case PP * DD:  proto  = (const float*)d_in[i];     break;
        }
    }
    if (!x || !labels || !W || !b || !proto) {
        x      = (const float*)d_in[0];
        labels = (const long long*)d_in[1];
        W      = (const float*)d_in[2];
        b      = (const float*)d_in[3];
        proto  = (const float*)d_in[4];
    }
    float* out = (float*)d_out;

    cudaFuncSetAttribute(k_gemm_hmma, cudaFuncAttributeMaxDynamicSharedMemorySize,
                         SMEM_GEMM);

    k_init     <<<1, 64>>>();
    k_proto    <<<PP, 256>>>(proto);
    k_convX    <<<NS * IND / 4 / 256, 256>>>(x);
    k_convW    <<<IND * DD / 256, 256>>>(W);
    k_gemm_hmma<<<dim3(NS / 128, DD / 64), 256, SMEM_GEMM>>>(b);
    k_stats    <<<NS / SB, 256>>>(proto, labels);
    k_tokens   <<<(NS * PP * DD / 4) / 256, 256>>>(proto, out);
    k_final    <<<1, 64>>>(out, out_size - 1);
}

// round 6
// speedup vs baseline: 1.4747x; 1.1149x over previous
#include <cuda_runtime.h>
#include <cuda_bf16.h>
#include <math.h>
#include <float.h>
#include <stdint.h>

// ---------------------------------------------------------------------------
// Problem constants
// ---------------------------------------------------------------------------
#define NS   4096        // samples
#define IND  768         // input dim
#define DD   256         // prototype dim
#define PP   64          // prototypes
#define PPOS 32          // P/2
#define SB   16          // samples per fused stats/tokens block

// ---------------------------------------------------------------------------
// Device scratch (static — no runtime allocation allowed)
// ---------------------------------------------------------------------------
__device__ float          g_z[NS * DD];          // z = xW+b (4 MB, written once)
__device__ __nv_bfloat16  g_xhi[NS * IND];       // x hi bf16, [M][K]
__device__ __nv_bfloat16  g_xlo[NS * IND];       // x lo bf16
__device__ __nv_bfloat16  g_bhi[DD * IND];       // W^T hi, [N][K]
__device__ __nv_bfloat16  g_blo[DD * IND];       // W^T lo
__device__ float          g_pnorm2[PP];
__device__ float          g_pnorm_inv[PP];
__device__ float          g_pp_part[PP];         // per-block pp partials
__device__ unsigned int   g_minBits[PP];
__device__ float          g_pz_sum;
__device__ float          g_cl_sum;
__device__ int            g_num_cnt;

__device__ __forceinline__ float warpSum(float v) {
#pragma unroll
    for (int o = 16; o; o >>= 1) v += __shfl_xor_sync(0xffffffffu, v, o);
    return v;
}

__device__ __forceinline__ uint32_t smem_u32(const void* p) {
    uint32_t a;
    asm("{ .reg .u64 t; cvta.to.shared.u64 t, %1; cvt.u32.u64 %0, t; }"
        : "=r"(a) : "l"(p));
    return a;
}

__device__ __forceinline__ void cp16(uint32_t sdst, const void* gsrc) {
    asm volatile("cp.async.cg.shared.global [%0], [%1], 16;"
                 :: "r"(sdst), "l"(gsrc) : "memory");
}

// m16n8k16 row.col f32.bf16.bf16.f32
__device__ __forceinline__ void mma16816(float (&d)[4], const uint32_t (&a)[4],
                                         const uint32_t (&b)[2]) {
    asm volatile(
        "mma.sync.aligned.m16n8k16.row.col.f32.bf16.bf16.f32 "
        "{%0,%1,%2,%3}, {%4,%5,%6,%7}, {%8,%9}, {%0,%1,%2,%3};"
        : "+f"(d[0]), "+f"(d[1]), "+f"(d[2]), "+f"(d[3])
        : "r"(a[0]), "r"(a[1]), "r"(a[2]), "r"(a[3]),
          "r"(b[0]), "r"(b[1]));
}

// GEMM smem layout (bf16, padded stride 72 bf16)
#define ASTR     72
#define OFF_AHI  0
#define OFF_ALO  18432            // 128*72*2
#define OFF_BHI  36864
#define OFF_BLO  46080            // +64*72*2
#define GBUF     55296
#define SMEM_GEMM (2 * GBUF)      // 110592 B

// ---------------------------------------------------------------------------
// K_proto: per-prototype norms + pairwise-distance partials (race-free)
// ---------------------------------------------------------------------------
__global__ void k_proto(const float* __restrict__ proto) {
    const int i = blockIdx.x;
    const int t = threadIdx.x;
    __shared__ float pi[DD];
    __shared__ float red[8];
    __shared__ float ddist[PP];

    float v = proto[i * DD + t];
    pi[t] = v;
    float nrm = warpSum(v * v);
    if ((t & 31) == 0) red[t >> 5] = nrm;
    __syncthreads();
    if (t == 0) {
        float s = 0.f;
#pragma unroll
        for (int w = 0; w < 8; w++) s += red[w];
        g_pnorm2[i]    = s;
        g_pnorm_inv[i] = 1.0f / fmaxf(sqrtf(s), 1e-8f);
    }
    __syncthreads();

    const int j = t >> 2;
    const int q = t & 3;
    const float* pj = proto + j * DD + q * 64;
    float s = 0.f;
#pragma unroll 8
    for (int d = 0; d < 64; d++) {
        float df = pi[q * 64 + d] - pj[d];
        s += df * df;
    }
    s += __shfl_down_sync(0xffffffffu, s, 1);
    s += __shfl_down_sync(0xffffffffu, s, 2);
    if (q == 0) ddist[j] = (j == i) ? 0.f : sqrtf(fmaxf(s, 0.f));
    __syncthreads();
    if (t == 0) {
        float acc = 0.f;
#pragma unroll
        for (int k = 0; k < PP; k++) acc += ddist[k];
        g_pp_part[i] = acc;           // per-block partial, no atomics
    }
}

// ---------------------------------------------------------------------------
// K_convX: split x into hi/lo bf16; block 0 also initializes accumulators
// ---------------------------------------------------------------------------
__global__ __launch_bounds__(256)
void k_convX(const float* __restrict__ X) {
    if (blockIdx.x == 0) {
        const int t = threadIdx.x;
        if (t < PP) g_minBits[t] = 0x7f7fffffu;
        if (t == 0) { g_pz_sum = 0.f; g_cl_sum = 0.f; g_num_cnt = 0; }
    }
    const int i = blockIdx.x * 256 + threadIdx.x;       // float4 index
    const float4 v = ((const float4*)X)[i];
    const __nv_bfloat16 h0 = __float2bfloat16_rn(v.x);
    const __nv_bfloat16 h1 = __float2bfloat16_rn(v.y);
    const __nv_bfloat16 h2 = __float2bfloat16_rn(v.z);
    const __nv_bfloat16 h3 = __float2bfloat16_rn(v.w);
    const __nv_bfloat16 l0 = __float2bfloat16_rn(v.x - __bfloat162float(h0));
    const __nv_bfloat16 l1 = __float2bfloat16_rn(v.y - __bfloat162float(h1));
    const __nv_bfloat16 l2 = __float2bfloat16_rn(v.z - __bfloat162float(h2));
    const __nv_bfloat16 l3 = __float2bfloat16_rn(v.w - __bfloat162float(h3));
    const uint32_t hp0 = ((uint32_t)__bfloat16_as_ushort(h1) << 16) | __bfloat16_as_ushort(h0);
    const uint32_t hp1 = ((uint32_t)__bfloat16_as_ushort(h3) << 16) | __bfloat16_as_ushort(h2);
    const uint32_t lp0 = ((uint32_t)__bfloat16_as_ushort(l1) << 16) | __bfloat16_as_ushort(l0);
    const uint32_t lp1 = ((uint32_t)__bfloat16_as_ushort(l3) << 16) | __bfloat16_as_ushort(l2);
    ((uint2*)g_xhi)[i] = make_uint2(hp0, hp1);
    ((uint2*)g_xlo)[i] = make_uint2(lp0, lp1);
}

// ---------------------------------------------------------------------------
// K_convW: split W into hi/lo bf16, transposed to [N][K] via smem tiles.
// grid (24, 8): k-tile 32 x n-tile 32. Coalesced reads AND writes.
// ---------------------------------------------------------------------------
__global__ __launch_bounds__(256)
void k_convW(const float* __restrict__ W) {
    __shared__ float tile[32][33];
    const int k0 = blockIdx.x * 32;
    const int n0 = blockIdx.y * 32;
    const int tx = threadIdx.x & 31;
    const int ty = threadIdx.x >> 5;   // 0..7

    // read 32x32 tile of W[k][n], coalesced along n
#pragma unroll
    for (int r = 0; r < 4; r++) {
        const int k = ty + r * 8;
        tile[k][tx] = W[(size_t)(k0 + k) * DD + n0 + tx];
    }
    __syncthreads();

    // write transposed: g_b*(n, k), coalesced along k
#pragma unroll
    for (int r = 0; r < 4; r++) {
        const int n = ty + r * 8;
        const float w = tile[tx][n];
        const __nv_bfloat16 h = __float2bfloat16_rn(w);
        const __nv_bfloat16 l = __float2bfloat16_rn(w - __bfloat162float(h));
        const size_t o = (size_t)(n0 + n) * IND + k0 + tx;
        g_bhi[o] = h;
        g_blo[o] = l;
    }
}

// ---------------------------------------------------------------------------
// K_gemm_hmma: z = x @ W + b via mma.sync bf16x3 (hi*hi + hi*lo + lo*hi).
// CTA tile 128x64, K=768 in 12 chunks of 64, cp.async double-buffered.
// grid (32, 4) = 128 blocks, 256 threads (8 warps, warp tile 32x32).
// ---------------------------------------------------------------------------
__global__ __launch_bounds__(256, 1)
void k_gemm_hmma(const float* __restrict__ bias) {
    extern __shared__ __align__(128) char sm[];
    const uint32_t smb = smem_u32(sm);

    const int tid  = threadIdx.x;
    const int wid  = tid >> 5;
    const int lane = tid & 31;
    const int gid  = lane >> 2;
    const int tig  = lane & 3;
    const int m0   = blockIdx.x * 128;
    const int n0   = blockIdx.y * 64;
    const int wm   = (wid & 3) * 32;
    const int wn   = (wid >> 2) * 32;

    auto stage = [&](int buf, int c) {
        const uint32_t bb = smb + buf * GBUF;
        const int k0 = c * 64;
#pragma unroll
        for (int i = 0; i < 4; i++) {
            const int idx = i * 256 + tid;
            const int r = idx >> 3, c8 = idx & 7;
            const size_t g = (size_t)(m0 + r) * IND + k0 + c8 * 8;
            const uint32_t d = bb + OFF_AHI + (uint32_t)(r * ASTR + c8 * 8) * 2;
            cp16(d,                       g_xhi + g);
            cp16(d + (OFF_ALO - OFF_AHI), g_xlo + g);
        }
#pragma unroll
        for (int i = 0; i < 2; i++) {
            const int idx = i * 256 + tid;
            const int r = idx >> 3, c8 = idx & 7;
            const size_t g = (size_t)(n0 + r) * IND + k0 + c8 * 8;
            const uint32_t d = bb + OFF_BHI + (uint32_t)(r * ASTR + c8 * 8) * 2;
            cp16(d,                       g_bhi + g);
            cp16(d + (OFF_BLO - OFF_BHI), g_blo + g);
        }
        asm volatile("cp.async.commit_group;" ::: "memory");
    };

    float acc[2][4][4];
#pragma unroll
    for (int mt = 0; mt < 2; mt++)
#pragma unroll
        for (int nt = 0; nt < 4; nt++)
#pragma unroll
            for (int q = 0; q < 4; q++) acc[mt][nt][q] = 0.f;

    stage(0, 0);

#pragma unroll 1
    for (int c = 0; c < 12; c++) {
        const int buf = c & 1;
        if (c < 11) {
            stage(buf ^ 1, c + 1);
            asm volatile("cp.async.wait_group 1;" ::: "memory");
        } else {
            asm volatile("cp.async.wait_group 0;" ::: "memory");
        }
        __syncthreads();

        const char* bb = sm + buf * GBUF;
#pragma unroll
        for (int ks = 0; ks < 4; ks++) {
            const int kk = ks * 16;
            uint32_t Ahif[2][4], Alof[2][4];
#pragma unroll
            for (int mt = 0; mt < 2; mt++) {
                const int row = wm + mt * 16 + gid;
                const char* pa = bb + OFF_AHI + (uint32_t)(row * ASTR + kk + tig * 2) * 2;
                Ahif[mt][0] = *(const uint32_t*)(pa);
                Ahif[mt][1] = *(const uint32_t*)(pa + 8 * ASTR * 2);
                Ahif[mt][2] = *(const uint32_t*)(pa + 16);
                Ahif[mt][3] = *(const uint32_t*)(pa + 8 * ASTR * 2 + 16);
                const char* pl = pa + (OFF_ALO - OFF_AHI);
                Alof[mt][0] = *(const uint32_t*)(pl);
                Alof[mt][1] = *(const uint32_t*)(pl + 8 * ASTR * 2);
                Alof[mt][2] = *(const uint32_t*)(pl + 16);
                Alof[mt][3] = *(const uint32_t*)(pl + 8 * ASTR * 2 + 16);
            }
            uint32_t Bhif[4][2], Blof[4][2];
#pragma unroll
            for (int nt = 0; nt < 4; nt++) {
                const int row = wn + nt * 8 + gid;
                const char* pb = bb + OFF_BHI + (uint32_t)(row * ASTR + kk + tig * 2) * 2;
                Bhif[nt][0] = *(const uint32_t*)(pb);
                Bhif[nt][1] = *(const uint32_t*)(pb + 16);
                const char* pl = pb + (OFF_BLO - OFF_BHI);
                Blof[nt][0] = *(const uint32_t*)(pl);
                Blof[nt][1] = *(const uint32_t*)(pl + 16);
            }
#pragma unroll
            for (int mt = 0; mt < 2; mt++)
#pragma unroll
                for (int nt = 0; nt < 4; nt++) {
                    mma16816(acc[mt][nt], Ahif[mt], Bhif[nt]);
                    mma16816(acc[mt][nt], Ahif[mt], Blof[nt]);
                    mma16816(acc[mt][nt], Alof[mt], Bhif[nt]);
                }
        }
        __syncthreads();
    }

#pragma unroll
    for (int nt = 0; nt < 4; nt++) {
        const int col = n0 + wn + nt * 8 + tig * 2;
        const float2 bv = *(const float2*)&bias[col];
#pragma unroll
        for (int mt = 0; mt < 2; mt++) {
            const int row = m0 + wm + mt * 16 + gid;
            float2 v0 = make_float2(acc[mt][nt][0] + bv.x, acc[mt][nt][1] + bv.y);
            float2 v1 = make_float2(acc[mt][nt][2] + bv.x, acc[mt][nt][3] + bv.y);
            *(float2*)&g_z[(size_t)row * DD + col]       = v0;
            *(float2*)&g_z[(size_t)(row + 8) * DD + col] = v1;
        }
    }
}

// ---------------------------------------------------------------------------
// K_stats_tokens (fused): stats for 16 samples, then stream token writes
// directly from smem cos. grid = 256 blocks x 256 threads.
// ---------------------------------------------------------------------------
__global__ __launch_bounds__(256)
void k_stats_tokens(const float* __restrict__ proto,
                    const long long* __restrict__ labels,
                    float* __restrict__ out) {
    __shared__ __align__(16) float pT[64][68];   // proto chunk transposed [d][p]
    __shared__ float zsT[64][17];                // z chunk transposed [d][s]
    __shared__ float s_cos[SB][PP];              // cos for this block's samples
    __shared__ unsigned int bmin[PP];
    __shared__ float s_pz, s_cl;
    __shared__ int   s_cnt;

    const int tid = threadIdx.x;
    const int n0  = blockIdx.x * SB;
    const int s   = tid >> 4;       // 0..15 sample
    const int pg  = tid & 15;       // 0..15 proto group
    const int p0  = pg * 4;

    if (tid < PP) bmin[tid] = 0x7f7fffffu;
    if (tid == 0) { s_pz = 0.f; s_cl = 0.f; s_cnt = 0; }

    float acc[4] = {0.f, 0.f, 0.f, 0.f};
    float zn2p = 0.f;

#pragma unroll 1
    for (int ch = 0; ch < 4; ch++) {
        __syncthreads();
        {
            const float4 v = *(const float4*)&g_z[(size_t)(n0 + s) * DD + ch * 64 + pg * 4];
            zsT[pg * 4 + 0][s] = v.x;
            zsT[pg * 4 + 1][s] = v.y;
            zsT[pg * 4 + 2][s] = v.z;
            zsT[pg * 4 + 3][s] = v.w;
        }
#pragma unroll
        for (int i = 0; i < 4; i++) {
            const int idx = i * 256 + tid;
            const int p  = idx >> 4;
            const int d  = (idx & 15) * 4;
            const float4 v = __ldg((const float4*)&proto[p * DD + ch * 64 + d]);
            pT[d + 0][p] = v.x;
            pT[d + 1][p] = v.y;
            pT[d + 2][p] = v.z;
            pT[d + 3][p] = v.w;
        }
        __syncthreads();

#pragma unroll
        for (int j = 0; j < 4; j++) {
            const float v = zsT[pg * 4 + j][s];
            zn2p += v * v;
        }
#pragma unroll 4
        for (int d = 0; d < 64; d++) {
            const float4 pv = *(const float4*)&pT[d][p0];
            const float zv = zsT[d][s];
            acc[0] += zv * pv.x; acc[1] += zv * pv.y;
            acc[2] += zv * pv.z; acc[3] += zv * pv.w;
        }
    }

#pragma unroll
    for (int o = 1; o < 16; o <<= 1) zn2p += __shfl_xor_sync(0xffffffffu, zn2p, o);
    const float zn2 = zn2p;
    const float rz  = 1.0f / fmaxf(sqrtf(zn2), 1e-8f);

    const float4 pinv = __ldg((const float4*)&g_pnorm_inv[p0]);
    const float4 pn2  = __ldg((const float4*)&g_pnorm2[p0]);
    const float pinvs[4] = {pinv.x, pinv.y, pinv.z, pinv.w};
    const float pn2s[4]  = {pn2.x,  pn2.y,  pn2.z,  pn2.w};

    float cosv[4], dstv[4];
#pragma unroll
    for (int j = 0; j < 4; j++) {
        cosv[j] = acc[j] * rz * pinvs[j];
        dstv[j] = sqrtf(fmaxf(zn2 + pn2s[j] - 2.0f * acc[j], 0.f));
    }
    *(float4*)&s_cos[s][p0] = make_float4(cosv[0], cosv[1], cosv[2], cosv[3]);

#pragma unroll
    for (int j = 0; j < 4; j++)
        atomicMin(&bmin[p0 + j], __float_as_uint(dstv[j]));

    float minD = fminf(fminf(dstv[0], dstv[1]), fminf(dstv[2], dstv[3]));
    const float mx = fmaxf(fmaxf(cosv[0], cosv[1]), fmaxf(cosv[2], cosv[3]));
    const bool pos = (pg < 8);
    float mp = pos ? mx : -FLT_MAX;
    float mn = pos ? -FLT_MAX : mx;
    int cnt = (cosv[0] > 0.5f) + (cosv[1] > 0.5f) + (cosv[2] > 0.5f) + (cosv[3] > 0.5f);
#pragma unroll
    for (int o = 1; o < 16; o <<= 1) {
        minD = fminf(minD, __shfl_xor_sync(0xffffffffu, minD, o));
        mp   = fmaxf(mp,   __shfl_xor_sync(0xffffffffu, mp,   o));
        mn   = fmaxf(mn,   __shfl_xor_sync(0xffffffffu, mn,   o));
        cnt += __shfl_xor_sync(0xffffffffu, cnt, o);
    }
    if (pg == 0) {
        const long long lb = labels[n0 + s];
        atomicAdd(&s_pz, minD);
        atomicAdd(&s_cl, (lb == 1) ? (1.0f - mp) : (1.0f - mn));
        if (cnt > PP / 4) atomicAdd(&s_cnt, 1);
    }
    __syncthreads();

    if (tid == 0) {
        atomicAdd(&g_pz_sum, s_pz);
        atomicAdd(&g_cl_sum, s_cl);
        if (s_cnt) atomicAdd(&g_num_cnt, s_cnt);
    }
    if (tid < PP) atomicMin(&g_minBits[tid], bmin[tid]);

    // ---- token write phase: 16 samples x 64 p x 64 float4 = 65536 float4 ----
    // idx = it*256 + tid: d4 = tid&63 (fixed), p advances, coalesced stores.
    float4* out4 = (float4*)out + (size_t)n0 * (PP * DD / 4);
    const float4* proto4 = (const float4*)proto;
#pragma unroll 4
    for (int it = 0; it < 256; it++) {
        const int idx = it * 256 + tid;
        const int nl  = idx >> 12;
        const int p   = (idx >> 6) & 63;
        const int d4  = idx & 63;
        const float c = s_cos[nl][p];
        const float4 pr = __ldg(proto4 + p * 64 + d4);
        out4[idx] = make_float4(c * pr.x, c * pr.y, c * pr.z, c * pr.w);
    }
}

// ---------------------------------------------------------------------------
// K_final: combine scalar loss terms (sums pp partials too)
// ---------------------------------------------------------------------------
__global__ void k_final(float* __restrict__ out, int loss_idx) {
    __shared__ float s[PP];
    __shared__ float pp[PP];
    const int t = threadIdx.x;
    if (t < PP) {
        s[t]  = __uint_as_float(g_minBits[t]);
        pp[t] = g_pp_part[t];
    }
    __syncthreads();
    if (t == 0) {
        float zp = 0.f, pps = 0.f;
#pragma unroll
        for (int k = 0; k < PP; k++) { zp += s[k]; pps += pp[k]; }
        const float l_zp  = zp / (float)PP;
        const float l_pz  = g_pz_sum / (float)NS;
        const float l_pp  = pps / (float)(PP * (PP - 1));
        const float l_num = (float)g_num_cnt;
        const float l_cl  = g_cl_sum / (float)NS;
        out[loss_idx] = l_zp + l_pz + l_pp + l_num + l_cl + l_cl;
    }
}

// ---------------------------------------------------------------------------
// kernel_launch
// ---------------------------------------------------------------------------
extern "C" void kernel_launch(void* const* d_in, const int* in_sizes, int n_in,
                              void* d_out, int out_size) {
    const float*     x      = nullptr;
    const long long* labels = nullptr;
    const float*     W      = nullptr;
    const float*     b      = nullptr;
    const float*     proto  = nullptr;
    for (int i = 0; i < n_in; i++) {
        switch (in_sizes[i]) {
            case NS * IND: x      = (const float*)d_in[i];     break;
            case NS:       labels = (const long long*)d_in[i]; break;
            case IND * DD: W      = (const float*)d_in[i];     break;
            case DD:       b      = (const float*)d_in[i];     break;
            case PP * DD:  proto  = (const float*)d_in[i];     break;
        }
    }
    if (!x || !labels || !W || !b || !proto) {
        x      = (const float*)d_in[0];
        labels = (const long long*)d_in[1];
        W      = (const float*)d_in[2];
        b      = (const float*)d_in[3];
        proto  = (const float*)d_in[4];
    }
    float* out = (float*)d_out;

    cudaFuncSetAttribute(k_gemm_hmma, cudaFuncAttributeMaxDynamicSharedMemorySize,
                         SMEM_GEMM);

    k_proto       <<<PP, 256>>>(proto);                          // 1
    k_convX       <<<NS * IND / 4 / 256, 256>>>(x);              // 2 (+init)
    k_convW       <<<dim3(IND / 32, DD / 32), 256>>>(W);         // 3
    k_gemm_hmma   <<<dim3(NS / 128, DD / 64), 256, SMEM_GEMM>>>(b); // 4 <- profiled
    k_stats_tokens<<<NS / SB, 256>>>(proto, labels, out);        // 5
    k_final       <<<1, 64>>>(out, out_size - 1);                // 6
}